// round 5
// baseline (speedup 1.0000x reference)
#include <cuda_runtime.h>
#include <cstdint>

// Max-unpooling 2x2 stride 2, (32,64,112,112) -> (32,64,224,224).
// Non-overlapping windows => pure gather/expand, no atomics, no zero pass.
// 4 input pixels per thread: float4+int4 coalesced loads, one 256-bit
// st.global.v8.f32 per output row (top/bottom). Each v8 store is 32B/lane,
// lane-contiguous => 1KB contiguous warp burst, all full 128B lines.

static constexpr int H_IN   = 112;
static constexpr int W_IN   = 112;
static constexpr int W_OUT  = 224;
static constexpr int HW_IN  = H_IN * W_IN;      // 12544
static constexpr int HW_OUT = W_OUT * W_OUT;    // 50176

__device__ __forceinline__ void stg_v8(float* p,
    float a0, float a1, float a2, float a3,
    float a4, float a5, float a6, float a7)
{
    asm volatile(
        "st.global.v8.f32 [%0], {%1, %2, %3, %4, %5, %6, %7, %8};"
        :: "l"(p),
           "f"(a0), "f"(a1), "f"(a2), "f"(a3),
           "f"(a4), "f"(a5), "f"(a6), "f"(a7)
        : "memory");
}

__global__ void __launch_bounds__(256) unpool_kernel4(
    const float* __restrict__ fm,
    const int*   __restrict__ sw,
    float*       __restrict__ out,
    int total4)
{
    int t = blockIdx.x * blockDim.x + threadIdx.x;
    if (t >= total4) return;

    int idx = t * 4;                 // first of this thread's 4 input pixels
    int bc  = idx / HW_IN;
    int rem = idx - bc * HW_IN;
    int h   = rem / W_IN;
    int w   = rem - h * W_IN;        // multiple of 4

    float4 v = reinterpret_cast<const float4*>(fm)[t];
    int4   s = reinterpret_cast<const int4*>(sw)[t];

    // pixel j (value vj, switch sj), window at output (2h, 2(w+j)):
    //   top row:    col offset sj       if sj < 2
    //   bottom row: col offset sj - 2   if sj >= 2
    float t0 = (s.x == 0) ? v.x : 0.0f;
    float t1 = (s.x == 1) ? v.x : 0.0f;
    float t2 = (s.y == 0) ? v.y : 0.0f;
    float t3 = (s.y == 1) ? v.y : 0.0f;
    float t4 = (s.z == 0) ? v.z : 0.0f;
    float t5 = (s.z == 1) ? v.z : 0.0f;
    float t6 = (s.w == 0) ? v.w : 0.0f;
    float t7 = (s.w == 1) ? v.w : 0.0f;

    float b0 = (s.x == 2) ? v.x : 0.0f;
    float b1 = (s.x == 3) ? v.x : 0.0f;
    float b2 = (s.y == 2) ? v.y : 0.0f;
    float b3 = (s.y == 3) ? v.y : 0.0f;
    float b4 = (s.z == 2) ? v.z : 0.0f;
    float b5 = (s.z == 3) ? v.z : 0.0f;
    float b6 = (s.w == 2) ? v.w : 0.0f;
    float b7 = (s.w == 3) ? v.w : 0.0f;

    size_t obase = (size_t)bc * HW_OUT + (size_t)(2 * h) * W_OUT + 2 * w;
    stg_v8(out + obase,         t0, t1, t2, t3, t4, t5, t6, t7);  // row 2h
    stg_v8(out + obase + W_OUT, b0, b1, b2, b3, b4, b5, b6, b7);  // row 2h+1
}

extern "C" void kernel_launch(void* const* d_in, const int* in_sizes, int n_in,
                              void* d_out, int out_size)
{
    const float* fm = (const float*)d_in[0];
    const int*   sw = (const int*)d_in[1];
    float*       out = (float*)d_out;

    int total  = in_sizes[0];            // 32*64*112*112 = 25690112
    int total4 = (total + 3) / 4;        // 6422528
    int threads = 256;
    int blocks  = (total4 + threads - 1) / threads;  // 25088
    unpool_kernel4<<<blocks, threads>>>(fm, sw, out, total4);
}